// round 15
// baseline (speedup 1.0000x reference)
#include <cuda_runtime.h>
#include <cuda_bf16.h>

#define FULL 0xffffffffu

struct C2 { float x, y; };
__device__ __forceinline__ C2 mkc(float x, float y){ C2 c; c.x=x; c.y=y; return c; }
#define DUP(s) mkc((s),(s))

// ---------- packed f32x2 elementwise ops ----------
__device__ __forceinline__ C2 pfma(C2 a, C2 b, C2 c){
    C2 r;
    asm("{\n\t.reg .b64 A,B,C,D;\n\t"
        "mov.b64 A,{%2,%3};\n\t"
        "mov.b64 B,{%4,%5};\n\t"
        "mov.b64 C,{%6,%7};\n\t"
        "fma.rn.f32x2 D, A, B, C;\n\t"
        "mov.b64 {%0,%1}, D;\n\t}"
        : "=f"(r.x), "=f"(r.y)
        : "f"(a.x), "f"(a.y), "f"(b.x), "f"(b.y), "f"(c.x), "f"(c.y));
    return r;
}
__device__ __forceinline__ C2 pmul(C2 a, C2 b){
    C2 r;
    asm("{\n\t.reg .b64 A,B,D;\n\t"
        "mov.b64 A,{%2,%3};\n\t"
        "mov.b64 B,{%4,%5};\n\t"
        "mul.rn.f32x2 D, A, B;\n\t"
        "mov.b64 {%0,%1}, D;\n\t}"
        : "=f"(r.x), "=f"(r.y)
        : "f"(a.x), "f"(a.y), "f"(b.x), "f"(b.y));
    return r;
}
__device__ __forceinline__ C2 swapc(C2 v){ return mkc(v.y, v.x); }

// Mapping: 16 amplitudes/thread (k bits 0..3), 16 lanes/element, elem = lane bit 4.
//   odd qubits  (1,3,5,7) -> LOCAL k bits : q7->k1, q5->k2, q3->k4, q1->k8
//   even qubits (0,2,4,6) -> LANE bits    : q6->l1, q4->l2, q2->l4, q0->l8
template<int Q> struct QM {
    static constexpr bool local = (Q & 1) != 0;
    static constexpr int mask = local ? (1 << ((7 - Q) >> 1)) : (1 << ((6 - Q) >> 1));
};

__device__ __forceinline__ constexpr int cpop(int v){
    return (v&1)+((v>>1)&1)+((v>>2)&1)+((v>>3)&1);
}

__device__ __forceinline__ C2 cmul_s(C2 a, C2 b){
    return mkc(a.x*b.x - a.y*b.y, a.x*b.y + a.y*b.x);
}

// multiply a[k] by i^e(k), e(k) = (popc(k&MP) + 3*popc(k&MM)) & 3
template<int MP, int MM>
__device__ __forceinline__ void kdiag(C2 a[16]){
    #pragma unroll
    for (int k = 0; k < 16; ++k){
        const int e = (cpop(k & MP) + 3 * cpop(k & MM)) & 3;
        if (e == 1){ float t = a[k].x; a[k].x = -a[k].y; a[k].y =  t; }
        else if (e == 2){ a[k].x = -a[k].x; a[k].y = -a[k].y; }
        else if (e == 3){ float t = a[k].x; a[k].x =  a[k].y; a[k].y = -t; }
    }
}

// multiply ALL regs by complex W
__device__ __forceinline__ void diag_all(C2 a[16], C2 W){
    C2 P = DUP(W.x), Q = mkc(-W.y, W.y);
    #pragma unroll
    for (int k = 0; k < 16; ++k)
        a[k] = pfma(Q, swapc(a[k]), pmul(P, a[k]));
}

// multiply ALL regs by i where cb — SEL-based, ALU pipe
__device__ __forceinline__ void mul_i_sel(C2 a[16], bool cb){
    #pragma unroll
    for (int k = 0; k < 16; ++k){
        float nx = cb ? -a[k].y : a[k].x;
        float ny = cb ?  a[k].x : a[k].y;
        a[k].x = nx; a[k].y = ny;
    }
}

// multiply a[k] by w1^popc(k&MASK)
template<int MASK>
__device__ __forceinline__ void zpow(C2 a[16], C2 w1, C2 w2, C2 w3){
    #pragma unroll
    for (int k = 0; k < 16; ++k){
        const int p = cpop(k & MASK);
        if (p){
            C2 w = (p == 1) ? w1 : (p == 2) ? w2 : w3;
            a[k] = pfma(mkc(-w.y, w.y), swapc(a[k]), pmul(DUP(w.x), a[k]));
        }
    }
}

// FUSED RY(t1)->CX->RY(t2) on LOCAL target bit M; ctrl = runtime lane-uniform cb.
template<int M>
__device__ __forceinline__ void ry_loc_fused(C2 a[16], bool cb,
        float cs_, float ss_, float cd_, float sd_){
    C2 A0 = DUP(cb ? sd_ : cs_), B0 = DUP(cb ? cd_ : -ss_);
    C2 A1 = DUP(cb ? cd_ : ss_), B1 = DUP(cb ? -sd_ : cs_);
    #pragma unroll
    for (int k0 = 0; k0 < 16; ++k0) if (!(k0 & M)){
        int k1 = k0 | M;
        C2 a0 = a[k0], a1 = a[k1];
        a[k0] = pfma(A0, a0, pmul(B0, a1));
        a[k1] = pfma(A1, a0, pmul(B1, a1));
    }
}

// FUSED RY(t1)->CX->RY(t2) on LANE target bit LM; ctrl = LOCAL k-bit KM.
template<int LM, int KM>
__device__ __forceinline__ void ry_lane_fxk(C2 a[16],
        float cs_, float ss_, float cd_, float sd_, int hl){
    bool hi = (hl & LM) != 0;
    C2 CA0 = DUP(cs_),              CO0 = DUP(hi ? ss_ : -ss_);
    C2 CA1 = DUP(hi ? -sd_ : sd_),  CO1 = DUP(cd_);
    #pragma unroll
    for (int k = 0; k < 16; ++k){
        float px = __shfl_xor_sync(FULL, a[k].x, LM);
        float py = __shfl_xor_sync(FULL, a[k].y, LM);
        C2 p = mkc(px, py);
        if (k & KM) a[k] = pfma(CO1, p, pmul(CA1, a[k]));
        else        a[k] = pfma(CO0, p, pmul(CA0, a[k]));
    }
}

// X on local bit M, conditioned on runtime flag cb
template<int M>
__device__ __forceinline__ void xsel_local(C2 a[16], bool cb){
    #pragma unroll
    for (int k0 = 0; k0 < 16; ++k0) if (!(k0 & M)){
        int k1 = k0 | M;
        C2 t0 = a[k0], t1 = a[k1];
        a[k0] = cb ? t1 : t0;
        a[k1] = cb ? t0 : t1;
    }
}

// merged parity-0 CX stage: a[k] -> shfl_xor(a[k], k)
__device__ __forceinline__ void cx_shfl_id(C2 a[16]){
    #pragma unroll
    for (int k = 1; k < 16; ++k){
        a[k].x = __shfl_xor_sync(FULL, a[k].x, k);
        a[k].y = __shfl_xor_sync(FULL, a[k].y, k);
    }
}

// local RY on bit MT with per-k coeff selected by k&KM, then compile-time X if k&KM
template<int KM, int MT>
__device__ __forceinline__ void ry_local_sel_x(C2 a[16],
        float cs, float ss, float cd, float sd){
    #pragma unroll
    for (int k0 = 0; k0 < 16; ++k0) if (!(k0 & MT)){
        int k1 = k0 | MT;
        const float ce = (k0 & KM) ? cd : cs;
        const float se = (k0 & KM) ? sd : ss;
        C2 a0 = a[k0], a1 = a[k1];
        C2 n0 = pfma(DUP(ce), a0, pmul(DUP(-se), a1));
        C2 n1 = pfma(DUP(se), a0, pmul(DUP(ce), a1));
        if (k0 & KM){ a[k0] = n1; a[k1] = n0; }
        else        { a[k0] = n0; a[k1] = n1; }
    }
}

// compile-time local CX: control bit MC, target bit MT
template<int MC, int MT>
__device__ __forceinline__ void cx_local(C2 a[16]){
    #pragma unroll
    for (int k0 = 0; k0 < 16; ++k0) if ((k0 & MC) && !(k0 & MT)){
        int k1 = k0 | MT; C2 t = a[k0]; a[k0] = a[k1]; a[k1] = t;
    }
}

// ---------------- generic complex 1q gate ----------------
template<int Q>
__device__ __forceinline__ void g1(C2 a[16], C2 u00, C2 u01, C2 u10, C2 u11, int lane){
    constexpr int m = QM<Q>::mask;
    if constexpr (QM<Q>::local) {
        C2 x00 = DUP(u00.x), y00 = mkc(-u00.y, u00.y);
        C2 x01 = DUP(u01.x), y01 = mkc(-u01.y, u01.y);
        C2 x10 = DUP(u10.x), y10 = mkc(-u10.y, u10.y);
        C2 x11 = DUP(u11.x), y11 = mkc(-u11.y, u11.y);
        #pragma unroll
        for (int k0 = 0; k0 < 16; ++k0) if (!(k0 & m)) {
            int k1 = k0 | m;
            C2 a0 = a[k0], a1 = a[k1];
            C2 a0s = swapc(a0), a1s = swapc(a1);
            C2 t0 = pmul(x00, a0); t0 = pfma(y00, a0s, t0);
            t0 = pfma(x01, a1, t0); t0 = pfma(y01, a1s, t0);
            C2 t1 = pmul(x10, a0); t1 = pfma(y10, a0s, t1);
            t1 = pfma(x11, a1, t1); t1 = pfma(y11, a1s, t1);
            a[k0] = t0; a[k1] = t1;
        }
    } else {
        bool hi = (lane & m) != 0;
        C2 xA = hi ? DUP(u11.x) : DUP(u00.x);
        C2 yA = hi ? mkc(-u11.y, u11.y) : mkc(-u00.y, u00.y);
        C2 xB = hi ? DUP(u10.x) : DUP(u01.x);
        C2 yB = hi ? mkc(-u10.y, u10.y) : mkc(-u01.y, u01.y);
        #pragma unroll
        for (int k = 0; k < 16; ++k) {
            float px = __shfl_xor_sync(FULL, a[k].x, m);
            float py = __shfl_xor_sync(FULL, a[k].y, m);
            C2 t = pmul(xA, a[k]); t = pfma(yA, swapc(a[k]), t);
            t = pfma(xB, mkc(px, py), t); t = pfma(yB, mkc(py, px), t);
            a[k] = t;
        }
    }
}

// ---------------- CRX (packed; shuffle value last-in-chain) ----------------
template<int QC, int QT>
__device__ __forceinline__ void gcrx(C2 a[16], float c, float s, int lane){
    constexpr int mc = QM<QC>::mask, mt = QM<QT>::mask;
    if constexpr (QM<QC>::local && QM<QT>::local) {
        C2 c2 = DUP(c), sn = mkc(s, -s);
        #pragma unroll
        for (int k0 = 0; k0 < 16; ++k0) if ((k0 & mc) && !(k0 & mt)) {
            int k1 = k0 | mt;
            C2 a0 = a[k0], a1 = a[k1];
            a[k0] = pfma(c2, a0, pmul(sn, swapc(a1)));
            a[k1] = pfma(c2, a1, pmul(sn, swapc(a0)));
        }
    } else if constexpr (QM<QC>::local) {
        C2 c2 = DUP(c), sn = mkc(s, -s);
        #pragma unroll
        for (int k = 0; k < 16; ++k) if (k & mc) {
            float px = __shfl_xor_sync(FULL, a[k].x, mt);
            float py = __shfl_xor_sync(FULL, a[k].y, mt);
            a[k] = pfma(sn, mkc(py, px), pmul(c2, a[k]));
        }
    } else if constexpr (QM<QT>::local) {
        bool cb = (lane & mc) != 0;
        C2 c2 = DUP(cb ? c : 1.0f);
        C2 sn = cb ? mkc(s, -s) : mkc(0.f, 0.f);
        #pragma unroll
        for (int k0 = 0; k0 < 16; ++k0) if (!(k0 & mt)) {
            int k1 = k0 | mt;
            C2 a0 = a[k0], a1 = a[k1];
            a[k0] = pfma(c2, a0, pmul(sn, swapc(a1)));
            a[k1] = pfma(c2, a1, pmul(sn, swapc(a0)));
        }
    } else {
        bool cb = (lane & mc) != 0;
        C2 c2 = DUP(cb ? c : 1.0f);
        C2 sn = cb ? mkc(s, -s) : mkc(0.f, 0.f);
        #pragma unroll
        for (int k = 0; k < 16; ++k) {
            float px = __shfl_xor_sync(FULL, a[k].x, mt);
            float py = __shfl_xor_sync(FULL, a[k].y, mt);
            a[k] = pfma(sn, mkc(py, px), pmul(c2, a[k]));
        }
    }
}

// ---------------- real-state encode gates ----------------
template<int Q>
__device__ __forceinline__ void gryR(float r[16], float c, float s, int lane){
    constexpr int m = QM<Q>::mask;
    C2 c2 = DUP(c);
    if constexpr (QM<Q>::local) {
        if constexpr (m == 1) {
            C2 snn = mkc(-s, s);
            #pragma unroll
            for (int j = 0; j < 8; ++j) {
                C2 v = mkc(r[2*j], r[2*j+1]);
                C2 res = pfma(snn, swapc(v), pmul(c2, v));
                r[2*j] = res.x; r[2*j+1] = res.y;
            }
        } else {
            constexpr int pm = m >> 1;
            C2 s2 = DUP(s), ns2 = DUP(-s);
            #pragma unroll
            for (int j0 = 0; j0 < 8; ++j0) if (!(j0 & pm)) {
                int j1 = j0 | pm;
                C2 v0 = mkc(r[2*j0], r[2*j0+1]);
                C2 v1 = mkc(r[2*j1], r[2*j1+1]);
                C2 n0 = pfma(c2, v0, pmul(ns2, v1));
                C2 n1 = pfma(s2, v0, pmul(c2, v1));
                r[2*j0] = n0.x; r[2*j0+1] = n0.y;
                r[2*j1] = n1.x; r[2*j1+1] = n1.y;
            }
        }
    } else {
        C2 sg2 = (lane & m) ? DUP(s) : DUP(-s);
        #pragma unroll
        for (int j = 0; j < 8; ++j) {
            float px = __shfl_xor_sync(FULL, r[2*j],   m);
            float py = __shfl_xor_sync(FULL, r[2*j+1], m);
            C2 v = mkc(r[2*j], r[2*j+1]);
            C2 res = pfma(sg2, mkc(px, py), pmul(c2, v));
            r[2*j] = res.x; r[2*j+1] = res.y;
        }
    }
}

template<int QC, int QT>
__device__ __forceinline__ void gcxR(float r[16], int lane){
    constexpr int mc = QM<QC>::mask, mt = QM<QT>::mask;
    if constexpr (QM<QC>::local && QM<QT>::local) {
        #pragma unroll
        for (int k0 = 0; k0 < 16; ++k0) if ((k0 & mc) && !(k0 & mt)) {
            int k1 = k0 | mt; float t = r[k0]; r[k0] = r[k1]; r[k1] = t;
        }
    } else if constexpr (QM<QC>::local) {
        #pragma unroll
        for (int k = 0; k < 16; ++k) if (k & mc)
            r[k] = __shfl_xor_sync(FULL, r[k], mt);
    } else if constexpr (QM<QT>::local) {
        bool cb = (lane & mc) != 0;
        #pragma unroll
        for (int k0 = 0; k0 < 16; ++k0) if (!(k0 & mt)) {
            int k1 = k0 | mt;
            float t0 = r[k0], t1 = r[k1];
            r[k0] = cb ? t1 : t0;
            r[k1] = cb ? t0 : t1;
        }
    } else {
        bool cb = (lane & mc) != 0;
        #pragma unroll
        for (int k = 0; k < 16; ++k) {
            float pv = __shfl_xor_sync(FULL, r[k], mt);
            r[k] = cb ? pv : r[k];
        }
    }
}

__device__ __forceinline__ float wsum16(float v){
    #pragma unroll
    for (int o = 8; o; o >>= 1) v += __shfl_xor_sync(FULL, v, o);
    return v;
}

__device__ __forceinline__ void u3m(const float* p, C2& U00, C2& U01, C2& U10, C2& U11){
    float t = p[0], ph = p[1], la = p[2];
    float st, ct, sp, cp, sl, cl, spl, cpl;
    __sincosf(t * 0.5f, &st, &ct);
    __sincosf(ph, &sp, &cp);
    __sincosf(la, &sl, &cl);
    __sincosf(ph + la, &spl, &cpl);
    U00 = mkc(ct, 0.f);
    U01 = mkc(-cl*st, -sl*st);
    U10 = mkc( cp*st,  sp*st);
    U11 = mkc(cpl*ct, spl*ct);
}

__global__ void __launch_bounds__(64, 11)
qcnn_kernel(const float* __restrict__ x,
            const float* __restrict__ rz_p,  const float* __restrict__ ry_p,
            const float* __restrict__ ry2_p, const float* __restrict__ crx_p,
            const float* __restrict__ u3_p,  const float* __restrict__ u3b_p,
            const float* __restrict__ W1,    const float* __restrict__ b1,
            const float* __restrict__ W2,    const float* __restrict__ b2,
            float* __restrict__ out, int B)
{
    const int warp = (blockIdx.x * blockDim.x + threadIdx.x) >> 5;
    const int lane = threadIdx.x & 31;
    const int hl   = lane & 15;
    const int elem = warp * 2 + (lane >> 4);
    if (warp * 2 >= B) return;
    const int e = (elem < B) ? elem : (B - 1);

    // ================= encode (state purely REAL) =================
    float2 av = reinterpret_cast<const float2*>(x)[e * 16 + hl];
    float c0, s0, c1, s1;
    __sincosf(0.5f * av.x, &s0, &c0);
    __sincosf(0.5f * av.y, &s1, &c1);

    #define GETC(IDX) __shfl_sync(FULL, (((IDX) & 1) ? c1 : c0), (lane & 16) | ((IDX) >> 1))
    #define GETS(IDX) __shfl_sync(FULL, (((IDX) & 1) ? s1 : s0), (lane & 16) | ((IDX) >> 1))

    float r[16];
    {   // cycle 0: direct product state
        float qc[8], qs[8];
        #pragma unroll
        for (int q = 0; q < 8; ++q){ qc[q] = GETC(q); qs[q] = GETS(q); }
        float F = ((hl & 8) ? qs[0] : qc[0]) * ((hl & 4) ? qs[2] : qc[2])
                * ((hl & 2) ? qs[4] : qc[4]) * ((hl & 1) ? qs[6] : qc[6]);
        float u_[4] = { qc[1]*qc[3], qc[1]*qs[3], qs[1]*qc[3], qs[1]*qs[3] };
        float v_[4] = { qc[5]*qc[7], qc[5]*qs[7], qs[5]*qc[7], qs[5]*qs[7] };
        #pragma unroll
        for (int i = 0; i < 4; ++i) u_[i] *= F;
        #pragma unroll
        for (int k = 0; k < 16; ++k) r[k] = u_[k >> 2] * v_[k & 3];
    }

    #define RYQ(CY,Q) do { \
        const int idx_ = (CY)*8 + (Q); \
        float cc_ = GETC(idx_); \
        float ss_ = GETS(idx_); \
        gryR<Q>(r, cc_, ss_, lane); } while(0)

    #define CX_RING() \
        gcxR<0,1>(r,lane); gcxR<1,2>(r,lane); gcxR<2,3>(r,lane); gcxR<3,4>(r,lane); \
        gcxR<4,5>(r,lane); gcxR<5,6>(r,lane); gcxR<6,7>(r,lane); gcxR<7,0>(r,lane);

    #define ENC_CYC(CY) \
        RYQ(CY,0); RYQ(CY,1); RYQ(CY,2); RYQ(CY,3); \
        RYQ(CY,4); RYQ(CY,5); RYQ(CY,6); RYQ(CY,7); \
        CX_RING()

    CX_RING()
    ENC_CYC(1) ENC_CYC(2) ENC_CYC(3)

    // ================= dual-state psi phase =================
    C2 A[16], Bs[16];
    #pragma unroll
    for (int k = 0; k < 16; ++k){ A[k] = mkc(r[k], 0.f); Bs[k] = A[k]; }

    // --- psi0 layer-0 parameters ---
    float zs0, zc0;
    __sincosf(rz_p[0], &zs0, &zc0);
    C2 w1 = mkc(zc0, zs0);
    C2 w2 = cmul_s(w1, w1);
    C2 w3 = cmul_s(w2, w1);
    float yc, ys, y2c, y2s;
    __sincosf(ry_p[0]  * 0.5f, &ys,  &yc);
    __sincosf(ry2_p[0] * 0.5f, &y2s, &y2c);
    float cs_ = yc*y2c - ys*y2s, ss_ = ys*y2c + yc*y2s;
    float cd_ = yc*y2c + ys*y2s, sd_ = ys*y2c - yc*y2s;
    C2 Wd;   // merged RZ diag for parity-0
    {
        C2 w4 = cmul_s(w2, w2);
        int p = __popc((unsigned)hl);
        Wd = (p & 1) ? w1 : mkc(1.f, 0.f);
        if (p & 2) Wd = cmul_s(Wd, w2);
        Wd.x = (p & 4) ? w4.x : Wd.x;
        Wd.y = (p & 4) ? w4.y : Wd.y;
    }
    float xc0, xs0;
    __sincosf(crx_p[0] * 0.5f, &xs0, &xc0);

    // ====== chunk 1: psi1-l0 CRX ladder  ||  psi0-l0 parity-0 ======
    gcrx<0,1>(Bs, xc0, xs0, lane);
    gcrx<2,3>(Bs, xc0, xs0, lane);
    gcrx<4,5>(Bs, xc0, xs0, lane);
    gcrx<6,7>(Bs, xc0, xs0, lane);

    kdiag<0, 15>(A);
    cx_shfl_id(A);

    gcrx<1,2>(Bs, xc0, xs0, lane);
    gcrx<3,4>(Bs, xc0, xs0, lane);
    gcrx<5,6>(Bs, xc0, xs0, lane);

    diag_all(A, Wd);
    ry_loc_fused<8>(A, (hl & 8) != 0, cs_, ss_, cd_, sd_);
    ry_loc_fused<4>(A, (hl & 4) != 0, cs_, ss_, cd_, sd_);

    // ====== chunk 2: psi1-l0 U3  ||  psi0-l0 parity-0 tail ======
    {
        C2 U00, U01, U10, U11;
        u3m(u3b_p, U00, U01, U10, U11);
        g1<1>(Bs, U00, U01, U10, U11, lane);
        g1<3>(Bs, U00, U01, U10, U11, lane);

        ry_loc_fused<2>(A, (hl & 2) != 0, cs_, ss_, cd_, sd_);
        ry_loc_fused<1>(A, (hl & 1) != 0, cs_, ss_, cd_, sd_);

        g1<5>(Bs, U00, U01, U10, U11, lane);
        g1<7>(Bs, U00, U01, U10, U11, lane);

        cx_shfl_id(A);
        mul_i_sel(A, (hl & 8) != 0);
    }

    // ====== chunk 3: psi1-l1 CRX  ||  psi0-l0 parity-1 ======
    xsel_local<8>(A, (hl & 4) != 0);
    xsel_local<4>(A, (hl & 2) != 0);
    xsel_local<2>(A, (hl & 1) != 0);
    zpow<14>(A, w1, w2, w3);

    {
        float xc1, xs1;
        __sincosf(crx_p[1] * 0.5f, &xs1, &xc1);
        gcrx<1,3>(Bs, xc1, xs1, lane);
        gcrx<5,7>(Bs, xc1, xs1, lane);

        ry_lane_fxk<4, 8>(A, cs_, ss_, cd_, sd_, hl);

        gcrx<3,5>(Bs, xc1, xs1, lane);

        ry_lane_fxk<2, 4>(A, cs_, ss_, cd_, sd_, hl);
        ry_lane_fxk<1, 2>(A, cs_, ss_, cd_, sd_, hl);

        xsel_local<8>(A, (hl & 4) != 0);
        xsel_local<4>(A, (hl & 2) != 0);
        xsel_local<2>(A, (hl & 1) != 0);
        kdiag<14, 0>(A);
    }

    // ====== chunk 4: psi0-l0 U3  ||  psi1-l1 U3 ======
    {
        C2 U00, U01, U10, U11;   // psi0 U3a layer0
        u3m(u3_p, U00, U01, U10, U11);
        C2 V00, V01, V10, V11;   // psi1 U3b layer1
        u3m(u3b_p + 3, V00, V01, V10, V11);

        g1<1>(A, U00, U01, U10, U11, lane);
        g1<3>(Bs, V00, V01, V10, V11, lane);
        g1<3>(A, U00, U01, U10, U11, lane);
        g1<7>(Bs, V00, V01, V10, V11, lane);
        g1<5>(A, U00, U01, U10, U11, lane);
        g1<7>(A, U00, U01, U10, U11, lane);
    }

    // ====== chunk 5: psi0 layer-1  ||  psi1 measure + MLP prefetch ======
    // layer-1 params first (MUFU latency overlaps the measure below)
    float zs, zc;
    __sincosf(rz_p[1], &zs, &zc);
    C2 v1 = mkc(zc, zs);
    C2 v2 = cmul_s(v1, v1);
    float yc1, ys1, y2c1, y2s1;
    __sincosf(ry_p[1]  * 0.5f, &ys1,  &yc1);
    __sincosf(ry2_p[1] * 0.5f, &y2s1, &y2c1);
    const float cs1 = yc1*y2c1 - ys1*y2s1, ss1 = ys1*y2c1 + yc1*y2s1;
    const float cd1 = yc1*y2c1 + ys1*y2s1, sd1 = ys1*y2c1 - yc1*y2s1;

    // MLP weight prefetch (independent LDGs, latency hidden under psi0-l1)
    float4 w1v = make_float4(0.f,0.f,0.f,0.f);
    float bb1 = 0.f, ww2 = 0.f;
    if (hl < 15) {
        w1v = __ldg(reinterpret_cast<const float4*>(W1) + hl);
        bb1 = __ldg(b1 + hl);
        ww2 = __ldg(W2 + hl);
    }
    const float bb2 = __ldg(b2);

    // psi1 measure: partial sums (FMA chain, independent of psi0-l1)
    float p3b = 0.f, p7b = 0.f;
    #pragma unroll
    for (int k = 0; k < 16; ++k) {
        float m = fmaf(Bs[k].x, Bs[k].x, Bs[k].y * Bs[k].y);
        p3b += (k & 4) ? -m : m;
        p7b += (k & 1) ? -m : m;
    }

    // psi0 layer-1 parity-0 (independent of the Bs reductions above)
    kdiag<0, 5>(A);
    cx_local<4, 8>(A);
    cx_local<1, 2>(A);
    zpow<10>(A, v1, v2, v2);

    float f2 = wsum16(p3b);        // Bs reductions woven between A stages
    ry_local_sel_x<8, 4>(A, cs1, ss1, cd1, sd1);
    float f3 = wsum16(p7b);
    ry_local_sel_x<2, 1>(A, cs1, ss1, cd1, sd1);

    cx_local<4, 8>(A);
    cx_local<1, 2>(A);
    kdiag<10, 2>(A);

    // psi0 layer-1 parity-1
    cx_local<2, 4>(A);
    zpow<4>(A, v1, v2, v2);
    ry_local_sel_x<4, 2>(A, cs1, ss1, cd1, sd1);
    cx_local<2, 4>(A);
    kdiag<4, 0>(A);

    {
        C2 U00, U01, U10, U11;
        u3m(u3_p + 3, U00, U01, U10, U11);
        g1<3>(A, U00, U01, U10, U11, lane);
        g1<7>(A, U00, U01, U10, U11, lane);
    }

    float f0, f1;
    {
        float p3 = 0.f, p7 = 0.f;
        #pragma unroll
        for (int k = 0; k < 16; ++k) {
            float m = fmaf(A[k].x, A[k].x, A[k].y * A[k].y);
            p3 += (k & 4) ? -m : m;
            p7 += (k & 1) ? -m : m;
        }
        f0 = wsum16(p3);
        f1 = wsum16(p7);
    }

    // ================= MLP head =================
    float hv = 0.f;
    if (hl < 15) {
        float z = bb1;
        z = fmaf(w1v.x, f0, z);
        z = fmaf(w1v.y, f1, z);
        z = fmaf(w1v.z, f2, z);
        z = fmaf(w1v.w, f3, z);
        hv = tanhf(z) * ww2;
    }
    float s = wsum16(hv);
    if (hl == 0 && elem < B) {
        float zf = s + bb2;
        out[elem] = 1.0f / (1.0f + __expf(-zf));
    }
}

extern "C" void kernel_launch(void* const* d_in, const int* in_sizes, int n_in,
                              void* d_out, int out_size) {
    const float* x     = (const float*)d_in[0];
    const float* rz_p  = (const float*)d_in[1];
    const float* ry_p  = (const float*)d_in[2];
    const float* ry2_p = (const float*)d_in[3];
    const float* crx_p = (const float*)d_in[4];
    const float* u3_p  = (const float*)d_in[5];
    const float* u3b_p = (const float*)d_in[6];
    const float* W1    = (const float*)d_in[7];
    const float* b1    = (const float*)d_in[8];
    const float* W2    = (const float*)d_in[9];
    const float* b2    = (const float*)d_in[10];

    int B = in_sizes[0] / 32;          // x is (B, 32)
    const int threads = 64;            // 2 warps/block, 4 elements/block
    int blocks = (B + 3) / 4;
    qcnn_kernel<<<blocks, threads>>>(x, rz_p, ry_p, ry2_p, crx_p, u3_p, u3b_p,
                                     W1, b1, W2, b2, (float*)d_out, B);
}

// round 16
// speedup vs baseline: 1.0714x; 1.0714x over previous
#include <cuda_runtime.h>
#include <cuda_bf16.h>

#define FULL 0xffffffffu

struct C2 { float x, y; };
__device__ __forceinline__ C2 mkc(float x, float y){ C2 c; c.x=x; c.y=y; return c; }
#define DUP(s) mkc((s),(s))

// ---------- packed f32x2 elementwise ops ----------
__device__ __forceinline__ C2 pfma(C2 a, C2 b, C2 c){
    C2 r;
    asm("{\n\t.reg .b64 A,B,C,D;\n\t"
        "mov.b64 A,{%2,%3};\n\t"
        "mov.b64 B,{%4,%5};\n\t"
        "mov.b64 C,{%6,%7};\n\t"
        "fma.rn.f32x2 D, A, B, C;\n\t"
        "mov.b64 {%0,%1}, D;\n\t}"
        : "=f"(r.x), "=f"(r.y)
        : "f"(a.x), "f"(a.y), "f"(b.x), "f"(b.y), "f"(c.x), "f"(c.y));
    return r;
}
__device__ __forceinline__ C2 pmul(C2 a, C2 b){
    C2 r;
    asm("{\n\t.reg .b64 A,B,D;\n\t"
        "mov.b64 A,{%2,%3};\n\t"
        "mov.b64 B,{%4,%5};\n\t"
        "mul.rn.f32x2 D, A, B;\n\t"
        "mov.b64 {%0,%1}, D;\n\t}"
        : "=f"(r.x), "=f"(r.y)
        : "f"(a.x), "f"(a.y), "f"(b.x), "f"(b.y));
    return r;
}
__device__ __forceinline__ C2 swapc(C2 v){ return mkc(v.y, v.x); }

// Mapping: 16 amplitudes/thread (k bits 0..3), 16 lanes/element, elem = lane bit 4.
//   odd qubits  (1,3,5,7) -> LOCAL k bits : q7->k1, q5->k2, q3->k4, q1->k8
//   even qubits (0,2,4,6) -> LANE bits    : q6->l1, q4->l2, q2->l4, q0->l8
template<int Q> struct QM {
    static constexpr bool local = (Q & 1) != 0;
    static constexpr int mask = local ? (1 << ((7 - Q) >> 1)) : (1 << ((6 - Q) >> 1));
};

__device__ __forceinline__ constexpr int cpop(int v){
    return (v&1)+((v>>1)&1)+((v>>2)&1)+((v>>3)&1);
}

__device__ __forceinline__ C2 cmul_s(C2 a, C2 b){
    return mkc(a.x*b.x - a.y*b.y, a.x*b.y + a.y*b.x);
}

// multiply a[k] by i^e(k), e(k) = (popc(k&MP) + 3*popc(k&MM)) & 3
template<int MP, int MM>
__device__ __forceinline__ void kdiag(C2 a[16]){
    #pragma unroll
    for (int k = 0; k < 16; ++k){
        const int e = (cpop(k & MP) + 3 * cpop(k & MM)) & 3;
        if (e == 1){ float t = a[k].x; a[k].x = -a[k].y; a[k].y =  t; }
        else if (e == 2){ a[k].x = -a[k].x; a[k].y = -a[k].y; }
        else if (e == 3){ float t = a[k].x; a[k].x =  a[k].y; a[k].y = -t; }
    }
}

// multiply ALL regs by complex W
__device__ __forceinline__ void diag_all(C2 a[16], C2 W){
    C2 P = DUP(W.x), Q = mkc(-W.y, W.y);
    #pragma unroll
    for (int k = 0; k < 16; ++k)
        a[k] = pfma(Q, swapc(a[k]), pmul(P, a[k]));
}

// multiply ALL regs by i where cb — SEL-based, ALU pipe
__device__ __forceinline__ void mul_i_sel(C2 a[16], bool cb){
    #pragma unroll
    for (int k = 0; k < 16; ++k){
        float nx = cb ? -a[k].y : a[k].x;
        float ny = cb ?  a[k].x : a[k].y;
        a[k].x = nx; a[k].y = ny;
    }
}

// multiply a[k] by w1^popc(k&MASK)
template<int MASK>
__device__ __forceinline__ void zpow(C2 a[16], C2 w1, C2 w2, C2 w3){
    #pragma unroll
    for (int k = 0; k < 16; ++k){
        const int p = cpop(k & MASK);
        if (p){
            C2 w = (p == 1) ? w1 : (p == 2) ? w2 : w3;
            a[k] = pfma(mkc(-w.y, w.y), swapc(a[k]), pmul(DUP(w.x), a[k]));
        }
    }
}

// FUSED RY(t1)->CX->RY(t2) on LOCAL target bit M; ctrl = runtime lane-uniform cb.
template<int M>
__device__ __forceinline__ void ry_loc_fused(C2 a[16], bool cb,
        float cs_, float ss_, float cd_, float sd_){
    C2 A0 = DUP(cb ? sd_ : cs_), B0 = DUP(cb ? cd_ : -ss_);
    C2 A1 = DUP(cb ? cd_ : ss_), B1 = DUP(cb ? -sd_ : cs_);
    #pragma unroll
    for (int k0 = 0; k0 < 16; ++k0) if (!(k0 & M)){
        int k1 = k0 | M;
        C2 a0 = a[k0], a1 = a[k1];
        a[k0] = pfma(A0, a0, pmul(B0, a1));
        a[k1] = pfma(A1, a0, pmul(B1, a1));
    }
}

// FUSED RY(t1)->CX->RY(t2) on LANE target bit LM; ctrl = LOCAL k-bit KM.
template<int LM, int KM>
__device__ __forceinline__ void ry_lane_fxk(C2 a[16],
        float cs_, float ss_, float cd_, float sd_, int hl){
    bool hi = (hl & LM) != 0;
    C2 CA0 = DUP(cs_),              CO0 = DUP(hi ? ss_ : -ss_);
    C2 CA1 = DUP(hi ? -sd_ : sd_),  CO1 = DUP(cd_);
    #pragma unroll
    for (int k = 0; k < 16; ++k){
        float px = __shfl_xor_sync(FULL, a[k].x, LM);
        float py = __shfl_xor_sync(FULL, a[k].y, LM);
        C2 p = mkc(px, py);
        if (k & KM) a[k] = pfma(CO1, p, pmul(CA1, a[k]));
        else        a[k] = pfma(CO0, p, pmul(CA0, a[k]));
    }
}

// X on local bit M, conditioned on runtime flag cb
template<int M>
__device__ __forceinline__ void xsel_local(C2 a[16], bool cb){
    #pragma unroll
    for (int k0 = 0; k0 < 16; ++k0) if (!(k0 & M)){
        int k1 = k0 | M;
        C2 t0 = a[k0], t1 = a[k1];
        a[k0] = cb ? t1 : t0;
        a[k1] = cb ? t0 : t1;
    }
}

// merged parity-0 CX stage: a[k] -> shfl_xor(a[k], k)
__device__ __forceinline__ void cx_shfl_id(C2 a[16]){
    #pragma unroll
    for (int k = 1; k < 16; ++k){
        a[k].x = __shfl_xor_sync(FULL, a[k].x, k);
        a[k].y = __shfl_xor_sync(FULL, a[k].y, k);
    }
}

// local RY on bit MT with per-k coeff selected by k&KM, then compile-time X if k&KM
template<int KM, int MT>
__device__ __forceinline__ void ry_local_sel_x(C2 a[16],
        float cs, float ss, float cd, float sd){
    #pragma unroll
    for (int k0 = 0; k0 < 16; ++k0) if (!(k0 & MT)){
        int k1 = k0 | MT;
        const float ce = (k0 & KM) ? cd : cs;
        const float se = (k0 & KM) ? sd : ss;
        C2 a0 = a[k0], a1 = a[k1];
        C2 n0 = pfma(DUP(ce), a0, pmul(DUP(-se), a1));
        C2 n1 = pfma(DUP(se), a0, pmul(DUP(ce), a1));
        if (k0 & KM){ a[k0] = n1; a[k1] = n0; }
        else        { a[k0] = n0; a[k1] = n1; }
    }
}

// compile-time local CX: control bit MC, target bit MT
template<int MC, int MT>
__device__ __forceinline__ void cx_local(C2 a[16]){
    #pragma unroll
    for (int k0 = 0; k0 < 16; ++k0) if ((k0 & MC) && !(k0 & MT)){
        int k1 = k0 | MT; C2 t = a[k0]; a[k0] = a[k1]; a[k1] = t;
    }
}

// ---------------- generic complex 1q gate ----------------
template<int Q>
__device__ __forceinline__ void g1(C2 a[16], C2 u00, C2 u01, C2 u10, C2 u11, int lane){
    constexpr int m = QM<Q>::mask;
    if constexpr (QM<Q>::local) {
        C2 x00 = DUP(u00.x), y00 = mkc(-u00.y, u00.y);
        C2 x01 = DUP(u01.x), y01 = mkc(-u01.y, u01.y);
        C2 x10 = DUP(u10.x), y10 = mkc(-u10.y, u10.y);
        C2 x11 = DUP(u11.x), y11 = mkc(-u11.y, u11.y);
        #pragma unroll
        for (int k0 = 0; k0 < 16; ++k0) if (!(k0 & m)) {
            int k1 = k0 | m;
            C2 a0 = a[k0], a1 = a[k1];
            C2 a0s = swapc(a0), a1s = swapc(a1);
            C2 t0 = pmul(x00, a0); t0 = pfma(y00, a0s, t0);
            t0 = pfma(x01, a1, t0); t0 = pfma(y01, a1s, t0);
            C2 t1 = pmul(x10, a0); t1 = pfma(y10, a0s, t1);
            t1 = pfma(x11, a1, t1); t1 = pfma(y11, a1s, t1);
            a[k0] = t0; a[k1] = t1;
        }
    } else {
        bool hi = (lane & m) != 0;
        C2 xA = hi ? DUP(u11.x) : DUP(u00.x);
        C2 yA = hi ? mkc(-u11.y, u11.y) : mkc(-u00.y, u00.y);
        C2 xB = hi ? DUP(u10.x) : DUP(u01.x);
        C2 yB = hi ? mkc(-u10.y, u10.y) : mkc(-u01.y, u01.y);
        #pragma unroll
        for (int k = 0; k < 16; ++k) {
            float px = __shfl_xor_sync(FULL, a[k].x, m);
            float py = __shfl_xor_sync(FULL, a[k].y, m);
            C2 t = pmul(xA, a[k]); t = pfma(yA, swapc(a[k]), t);
            t = pfma(xB, mkc(px, py), t); t = pfma(yB, mkc(py, px), t);
            a[k] = t;
        }
    }
}

// ---------------- CRX (packed; shuffle value last-in-chain) ----------------
template<int QC, int QT>
__device__ __forceinline__ void gcrx(C2 a[16], float c, float s, int lane){
    constexpr int mc = QM<QC>::mask, mt = QM<QT>::mask;
    if constexpr (QM<QC>::local && QM<QT>::local) {
        C2 c2 = DUP(c), sn = mkc(s, -s);
        #pragma unroll
        for (int k0 = 0; k0 < 16; ++k0) if ((k0 & mc) && !(k0 & mt)) {
            int k1 = k0 | mt;
            C2 a0 = a[k0], a1 = a[k1];
            a[k0] = pfma(c2, a0, pmul(sn, swapc(a1)));
            a[k1] = pfma(c2, a1, pmul(sn, swapc(a0)));
        }
    } else if constexpr (QM<QC>::local) {
        C2 c2 = DUP(c), sn = mkc(s, -s);
        #pragma unroll
        for (int k = 0; k < 16; ++k) if (k & mc) {
            float px = __shfl_xor_sync(FULL, a[k].x, mt);
            float py = __shfl_xor_sync(FULL, a[k].y, mt);
            a[k] = pfma(sn, mkc(py, px), pmul(c2, a[k]));
        }
    } else if constexpr (QM<QT>::local) {
        bool cb = (lane & mc) != 0;
        C2 c2 = DUP(cb ? c : 1.0f);
        C2 sn = cb ? mkc(s, -s) : mkc(0.f, 0.f);
        #pragma unroll
        for (int k0 = 0; k0 < 16; ++k0) if (!(k0 & mt)) {
            int k1 = k0 | mt;
            C2 a0 = a[k0], a1 = a[k1];
            a[k0] = pfma(c2, a0, pmul(sn, swapc(a1)));
            a[k1] = pfma(c2, a1, pmul(sn, swapc(a0)));
        }
    } else {
        bool cb = (lane & mc) != 0;
        C2 c2 = DUP(cb ? c : 1.0f);
        C2 sn = cb ? mkc(s, -s) : mkc(0.f, 0.f);
        #pragma unroll
        for (int k = 0; k < 16; ++k) {
            float px = __shfl_xor_sync(FULL, a[k].x, mt);
            float py = __shfl_xor_sync(FULL, a[k].y, mt);
            a[k] = pfma(sn, mkc(py, px), pmul(c2, a[k]));
        }
    }
}

// ---------------- real-state encode gates ----------------
template<int Q>
__device__ __forceinline__ void gryR(float r[16], float c, float s, int lane){
    constexpr int m = QM<Q>::mask;
    C2 c2 = DUP(c);
    if constexpr (QM<Q>::local) {
        if constexpr (m == 1) {
            C2 snn = mkc(-s, s);
            #pragma unroll
            for (int j = 0; j < 8; ++j) {
                C2 v = mkc(r[2*j], r[2*j+1]);
                C2 res = pfma(snn, swapc(v), pmul(c2, v));
                r[2*j] = res.x; r[2*j+1] = res.y;
            }
        } else {
            constexpr int pm = m >> 1;
            C2 s2 = DUP(s), ns2 = DUP(-s);
            #pragma unroll
            for (int j0 = 0; j0 < 8; ++j0) if (!(j0 & pm)) {
                int j1 = j0 | pm;
                C2 v0 = mkc(r[2*j0], r[2*j0+1]);
                C2 v1 = mkc(r[2*j1], r[2*j1+1]);
                C2 n0 = pfma(c2, v0, pmul(ns2, v1));
                C2 n1 = pfma(s2, v0, pmul(c2, v1));
                r[2*j0] = n0.x; r[2*j0+1] = n0.y;
                r[2*j1] = n1.x; r[2*j1+1] = n1.y;
            }
        }
    } else {
        C2 sg2 = (lane & m) ? DUP(s) : DUP(-s);
        #pragma unroll
        for (int j = 0; j < 8; ++j) {
            float px = __shfl_xor_sync(FULL, r[2*j],   m);
            float py = __shfl_xor_sync(FULL, r[2*j+1], m);
            C2 v = mkc(r[2*j], r[2*j+1]);
            C2 res = pfma(sg2, mkc(px, py), pmul(c2, v));
            r[2*j] = res.x; r[2*j+1] = res.y;
        }
    }
}

template<int QC, int QT>
__device__ __forceinline__ void gcxR(float r[16], int lane){
    constexpr int mc = QM<QC>::mask, mt = QM<QT>::mask;
    if constexpr (QM<QC>::local && QM<QT>::local) {
        #pragma unroll
        for (int k0 = 0; k0 < 16; ++k0) if ((k0 & mc) && !(k0 & mt)) {
            int k1 = k0 | mt; float t = r[k0]; r[k0] = r[k1]; r[k1] = t;
        }
    } else if constexpr (QM<QC>::local) {
        #pragma unroll
        for (int k = 0; k < 16; ++k) if (k & mc)
            r[k] = __shfl_xor_sync(FULL, r[k], mt);
    } else if constexpr (QM<QT>::local) {
        bool cb = (lane & mc) != 0;
        #pragma unroll
        for (int k0 = 0; k0 < 16; ++k0) if (!(k0 & mt)) {
            int k1 = k0 | mt;
            float t0 = r[k0], t1 = r[k1];
            r[k0] = cb ? t1 : t0;
            r[k1] = cb ? t0 : t1;
        }
    } else {
        bool cb = (lane & mc) != 0;
        #pragma unroll
        for (int k = 0; k < 16; ++k) {
            float pv = __shfl_xor_sync(FULL, r[k], mt);
            r[k] = cb ? pv : r[k];
        }
    }
}

__device__ __forceinline__ float wsum16(float v){
    #pragma unroll
    for (int o = 8; o; o >>= 1) v += __shfl_xor_sync(FULL, v, o);
    return v;
}

__device__ __forceinline__ void u3m(const float* p, C2& U00, C2& U01, C2& U10, C2& U11){
    float t = p[0], ph = p[1], la = p[2];
    float st, ct, sp, cp, sl, cl, spl, cpl;
    __sincosf(t * 0.5f, &st, &ct);
    __sincosf(ph, &sp, &cp);
    __sincosf(la, &sl, &cl);
    __sincosf(ph + la, &spl, &cpl);
    U00 = mkc(ct, 0.f);
    U01 = mkc(-cl*st, -sl*st);
    U10 = mkc( cp*st,  sp*st);
    U11 = mkc(cpl*ct, spl*ct);
}

__global__ void __launch_bounds__(64, 10)
qcnn_kernel(const float* __restrict__ x,
            const float* __restrict__ rz_p,  const float* __restrict__ ry_p,
            const float* __restrict__ ry2_p, const float* __restrict__ crx_p,
            const float* __restrict__ u3_p,  const float* __restrict__ u3b_p,
            const float* __restrict__ W1,    const float* __restrict__ b1,
            const float* __restrict__ W2,    const float* __restrict__ b2,
            float* __restrict__ out, int B)
{
    const int warp = (blockIdx.x * blockDim.x + threadIdx.x) >> 5;
    const int lane = threadIdx.x & 31;
    const int hl   = lane & 15;
    const int elem = warp * 2 + (lane >> 4);
    if (warp * 2 >= B) return;
    const int e = (elem < B) ? elem : (B - 1);

    // ================= encode (state purely REAL) =================
    float2 av = reinterpret_cast<const float2*>(x)[e * 16 + hl];
    float c0, s0, c1, s1;
    __sincosf(0.5f * av.x, &s0, &c0);
    __sincosf(0.5f * av.y, &s1, &c1);

    #define GETC(IDX) __shfl_sync(FULL, (((IDX) & 1) ? c1 : c0), (lane & 16) | ((IDX) >> 1))
    #define GETS(IDX) __shfl_sync(FULL, (((IDX) & 1) ? s1 : s0), (lane & 16) | ((IDX) >> 1))

    float r[16];
    {   // cycle 0: direct product state
        float qc[8], qs[8];
        #pragma unroll
        for (int q = 0; q < 8; ++q){ qc[q] = GETC(q); qs[q] = GETS(q); }
        float F = ((hl & 8) ? qs[0] : qc[0]) * ((hl & 4) ? qs[2] : qc[2])
                * ((hl & 2) ? qs[4] : qc[4]) * ((hl & 1) ? qs[6] : qc[6]);
        float u_[4] = { qc[1]*qc[3], qc[1]*qs[3], qs[1]*qc[3], qs[1]*qs[3] };
        float v_[4] = { qc[5]*qc[7], qc[5]*qs[7], qs[5]*qc[7], qs[5]*qs[7] };
        #pragma unroll
        for (int i = 0; i < 4; ++i) u_[i] *= F;
        #pragma unroll
        for (int k = 0; k < 16; ++k) r[k] = u_[k >> 2] * v_[k & 3];
    }

    #define RYQ(CY,Q) do { \
        const int idx_ = (CY)*8 + (Q); \
        float cc_ = GETC(idx_); \
        float ss_ = GETS(idx_); \
        gryR<Q>(r, cc_, ss_, lane); } while(0)

    #define CX_RING() \
        gcxR<0,1>(r,lane); gcxR<1,2>(r,lane); gcxR<2,3>(r,lane); gcxR<3,4>(r,lane); \
        gcxR<4,5>(r,lane); gcxR<5,6>(r,lane); gcxR<6,7>(r,lane); gcxR<7,0>(r,lane);

    #define ENC_CYC(CY) \
        RYQ(CY,0); RYQ(CY,1); RYQ(CY,2); RYQ(CY,3); \
        RYQ(CY,4); RYQ(CY,5); RYQ(CY,6); RYQ(CY,7); \
        CX_RING()

    CX_RING()
    ENC_CYC(1) ENC_CYC(2) ENC_CYC(3)

    // ================= dual-state psi phase =================
    C2 A[16], Bs[16];
    #pragma unroll
    for (int k = 0; k < 16; ++k){ A[k] = mkc(r[k], 0.f); Bs[k] = A[k]; }

    // --- psi0 layer-0 parameters ---
    float zs0, zc0;
    __sincosf(rz_p[0], &zs0, &zc0);
    C2 w1 = mkc(zc0, zs0);
    C2 w2 = cmul_s(w1, w1);
    C2 w3 = cmul_s(w2, w1);
    float yc, ys, y2c, y2s;
    __sincosf(ry_p[0]  * 0.5f, &ys,  &yc);
    __sincosf(ry2_p[0] * 0.5f, &y2s, &y2c);
    float cs_ = yc*y2c - ys*y2s, ss_ = ys*y2c + yc*y2s;
    float cd_ = yc*y2c + ys*y2s, sd_ = ys*y2c - yc*y2s;
    C2 Wd;   // merged RZ diag for parity-0
    {
        C2 w4 = cmul_s(w2, w2);
        int p = __popc((unsigned)hl);
        Wd = (p & 1) ? w1 : mkc(1.f, 0.f);
        if (p & 2) Wd = cmul_s(Wd, w2);
        Wd.x = (p & 4) ? w4.x : Wd.x;
        Wd.y = (p & 4) ? w4.y : Wd.y;
    }
    float xc0, xs0;
    __sincosf(crx_p[0] * 0.5f, &xs0, &xc0);

    // ====== chunk 1: psi1-l0 CRX ladder  ||  psi0-l0 parity-0 ======
    gcrx<0,1>(Bs, xc0, xs0, lane);
    gcrx<2,3>(Bs, xc0, xs0, lane);
    gcrx<4,5>(Bs, xc0, xs0, lane);
    gcrx<6,7>(Bs, xc0, xs0, lane);

    kdiag<0, 15>(A);
    cx_shfl_id(A);

    gcrx<1,2>(Bs, xc0, xs0, lane);
    gcrx<3,4>(Bs, xc0, xs0, lane);
    gcrx<5,6>(Bs, xc0, xs0, lane);

    diag_all(A, Wd);
    ry_loc_fused<8>(A, (hl & 8) != 0, cs_, ss_, cd_, sd_);
    ry_loc_fused<4>(A, (hl & 4) != 0, cs_, ss_, cd_, sd_);

    // ====== chunk 2: psi1-l0 U3  ||  psi0-l0 parity-0 tail ======
    {
        C2 U00, U01, U10, U11;
        u3m(u3b_p, U00, U01, U10, U11);
        g1<1>(Bs, U00, U01, U10, U11, lane);
        g1<3>(Bs, U00, U01, U10, U11, lane);

        ry_loc_fused<2>(A, (hl & 2) != 0, cs_, ss_, cd_, sd_);
        ry_loc_fused<1>(A, (hl & 1) != 0, cs_, ss_, cd_, sd_);

        g1<5>(Bs, U00, U01, U10, U11, lane);
        g1<7>(Bs, U00, U01, U10, U11, lane);

        cx_shfl_id(A);
        mul_i_sel(A, (hl & 8) != 0);
    }

    // ====== chunk 3: psi1-l1 CRX  ||  psi0-l0 parity-1 ======
    xsel_local<8>(A, (hl & 4) != 0);
    xsel_local<4>(A, (hl & 2) != 0);
    xsel_local<2>(A, (hl & 1) != 0);
    zpow<14>(A, w1, w2, w3);

    {
        float xc1, xs1;
        __sincosf(crx_p[1] * 0.5f, &xs1, &xc1);
        gcrx<1,3>(Bs, xc1, xs1, lane);
        gcrx<5,7>(Bs, xc1, xs1, lane);

        ry_lane_fxk<4, 8>(A, cs_, ss_, cd_, sd_, hl);

        gcrx<3,5>(Bs, xc1, xs1, lane);

        ry_lane_fxk<2, 4>(A, cs_, ss_, cd_, sd_, hl);
        ry_lane_fxk<1, 2>(A, cs_, ss_, cd_, sd_, hl);

        xsel_local<8>(A, (hl & 4) != 0);
        xsel_local<4>(A, (hl & 2) != 0);
        xsel_local<2>(A, (hl & 1) != 0);
        kdiag<14, 0>(A);
    }

    // ====== chunk 4: psi0-l0 U3  ||  psi1-l1 U3 ======
    {
        C2 U00, U01, U10, U11;   // psi0 U3a layer0
        u3m(u3_p, U00, U01, U10, U11);
        C2 V00, V01, V10, V11;   // psi1 U3b layer1
        u3m(u3b_p + 3, V00, V01, V10, V11);

        g1<1>(A, U00, U01, U10, U11, lane);
        g1<3>(Bs, V00, V01, V10, V11, lane);
        g1<3>(A, U00, U01, U10, U11, lane);
        g1<7>(Bs, V00, V01, V10, V11, lane);
        g1<5>(A, U00, U01, U10, U11, lane);
        g1<7>(A, U00, U01, U10, U11, lane);
    }

    // ====== chunk 5: psi0 layer-1  ||  psi1 measure + MLP prefetch ======
    float zs, zc;
    __sincosf(rz_p[1], &zs, &zc);
    C2 v1 = mkc(zc, zs);
    C2 v2 = cmul_s(v1, v1);
    float yc1, ys1, y2c1, y2s1;
    __sincosf(ry_p[1]  * 0.5f, &ys1,  &yc1);
    __sincosf(ry2_p[1] * 0.5f, &y2s1, &y2c1);
    const float cs1 = yc1*y2c1 - ys1*y2s1, ss1 = ys1*y2c1 + yc1*y2s1;
    const float cd1 = yc1*y2c1 + ys1*y2s1, sd1 = ys1*y2c1 - yc1*y2s1;

    // MLP weight prefetch (independent LDGs, latency hidden under psi0-l1)
    float4 w1v = make_float4(0.f,0.f,0.f,0.f);
    float bb1 = 0.f, ww2 = 0.f;
    if (hl < 15) {
        w1v = __ldg(reinterpret_cast<const float4*>(W1) + hl);
        bb1 = __ldg(b1 + hl);
        ww2 = __ldg(W2 + hl);
    }
    const float bb2 = __ldg(b2);

    // psi1 measure: partial sums (FMA chain, independent of psi0-l1)
    float p3b = 0.f, p7b = 0.f;
    #pragma unroll
    for (int k = 0; k < 16; ++k) {
        float m = fmaf(Bs[k].x, Bs[k].x, Bs[k].y * Bs[k].y);
        p3b += (k & 4) ? -m : m;
        p7b += (k & 1) ? -m : m;
    }

    // psi0 layer-1 parity-0 (independent of the Bs reductions above)
    kdiag<0, 5>(A);
    cx_local<4, 8>(A);
    cx_local<1, 2>(A);
    zpow<10>(A, v1, v2, v2);

    float f2 = wsum16(p3b);        // Bs reductions woven between A stages
    ry_local_sel_x<8, 4>(A, cs1, ss1, cd1, sd1);
    float f3 = wsum16(p7b);
    ry_local_sel_x<2, 1>(A, cs1, ss1, cd1, sd1);

    cx_local<4, 8>(A);
    cx_local<1, 2>(A);
    kdiag<10, 2>(A);

    // psi0 layer-1 parity-1
    cx_local<2, 4>(A);
    zpow<4>(A, v1, v2, v2);
    ry_local_sel_x<4, 2>(A, cs1, ss1, cd1, sd1);
    cx_local<2, 4>(A);
    kdiag<4, 0>(A);

    {
        C2 U00, U01, U10, U11;
        u3m(u3_p + 3, U00, U01, U10, U11);
        g1<3>(A, U00, U01, U10, U11, lane);
        g1<7>(A, U00, U01, U10, U11, lane);
    }

    float f0, f1;
    {
        float p3 = 0.f, p7 = 0.f;
        #pragma unroll
        for (int k = 0; k < 16; ++k) {
            float m = fmaf(A[k].x, A[k].x, A[k].y * A[k].y);
            p3 += (k & 4) ? -m : m;
            p7 += (k & 1) ? -m : m;
        }
        f0 = wsum16(p3);
        f1 = wsum16(p7);
    }

    // ================= MLP head =================
    float hv = 0.f;
    if (hl < 15) {
        float z = bb1;
        z = fmaf(w1v.x, f0, z);
        z = fmaf(w1v.y, f1, z);
        z = fmaf(w1v.z, f2, z);
        z = fmaf(w1v.w, f3, z);
        hv = tanhf(z) * ww2;
    }
    float s = wsum16(hv);
    if (hl == 0 && elem < B) {
        float zf = s + bb2;
        out[elem] = 1.0f / (1.0f + __expf(-zf));
    }
}

extern "C" void kernel_launch(void* const* d_in, const int* in_sizes, int n_in,
                              void* d_out, int out_size) {
    const float* x     = (const float*)d_in[0];
    const float* rz_p  = (const float*)d_in[1];
    const float* ry_p  = (const float*)d_in[2];
    const float* ry2_p = (const float*)d_in[3];
    const float* crx_p = (const float*)d_in[4];
    const float* u3_p  = (const float*)d_in[5];
    const float* u3b_p = (const float*)d_in[6];
    const float* W1    = (const float*)d_in[7];
    const float* b1    = (const float*)d_in[8];
    const float* W2    = (const float*)d_in[9];
    const float* b2    = (const float*)d_in[10];

    int B = in_sizes[0] / 32;          // x is (B, 32)
    const int threads = 64;            // 2 warps/block, 4 elements/block
    int blocks = (B + 3) / 4;
    qcnn_kernel<<<blocks, threads>>>(x, rz_p, ry_p, ry2_p, crx_p, u3_p, u3b_p,
                                     W1, b1, W2, b2, (float*)d_out, B);
}